// round 1
// baseline (speedup 1.0000x reference)
#include <cuda_runtime.h>
#include <cuda_bf16.h>
#include <cstdint>

#define N_NODES 100000
#define N_EDGES 1600000
#define HID 64
#define N_CLS 40

// ---------------- scratch (static device allocations; no cudaMalloc) -------
__device__ float g_h0[(size_t)N_NODES * HID];
__device__ float g_h1[(size_t)N_NODES * HID];
__device__ int   g_deg[N_NODES];
__device__ float g_inv[N_NODES];
__device__ int   g_rowptr[N_NODES + 1];
__device__ int   g_cursor[N_NODES];
__device__ int   g_col[N_EDGES];
__device__ int   g_bsums[128];
__device__ int   g_boffs[128];

// ---------------- CSR build ------------------------------------------------
__global__ void zero_deg_kernel() {
    int i = blockIdx.x * blockDim.x + threadIdx.x;
    if (i < N_NODES) g_deg[i] = 0;
}

__global__ void count_deg_kernel(const int* __restrict__ dst, int nE) {
    int e = blockIdx.x * blockDim.x + threadIdx.x;
    if (e < nE) atomicAdd(&g_deg[dst[e]], 1);
}

__device__ __forceinline__ int block_exscan(int val, int tid, int nthreads) {
    __shared__ int warp_s[32];
    int lane = tid & 31, wid = tid >> 5;
    int x = val;
#pragma unroll
    for (int d = 1; d < 32; d <<= 1) {
        int y = __shfl_up_sync(0xffffffffu, x, d);
        if (lane >= d) x += y;
    }
    if (lane == 31) warp_s[wid] = x;
    __syncthreads();
    int nw = nthreads >> 5;
    if (wid == 0) {
        int w = (lane < nw) ? warp_s[lane] : 0;
#pragma unroll
        for (int d = 1; d < 32; d <<= 1) {
            int y = __shfl_up_sync(0xffffffffu, w, d);
            if (lane >= d) w += y;
        }
        warp_s[lane] = w;  // inclusive scan of warp sums
    }
    __syncthreads();
    int base = (wid > 0) ? warp_s[wid - 1] : 0;
    return base + x - val;  // exclusive
}

__global__ void scan1_kernel() {
    int gid = blockIdx.x * 1024 + threadIdx.x;
    int v = (gid < N_NODES) ? g_deg[gid] : 0;
    int ex = block_exscan(v, threadIdx.x, 1024);
    if (gid < N_NODES) g_rowptr[gid] = ex;
    if (threadIdx.x == 1023) g_bsums[blockIdx.x] = ex + v;
}

__global__ void scan2_kernel(int nb) {
    int v = (threadIdx.x < nb) ? g_bsums[threadIdx.x] : 0;
    int ex = block_exscan(v, threadIdx.x, 128);
    if (threadIdx.x < nb) g_boffs[threadIdx.x] = ex;
}

__global__ void scan3_kernel(int nE) {
    int i = blockIdx.x * blockDim.x + threadIdx.x;
    if (i < N_NODES) {
        g_rowptr[i] += g_boffs[i >> 10];
        g_cursor[i] = 0;
        g_inv[i] = 1.0f / ((float)g_deg[i] + 1.0f);
    }
    if (i == 0) g_rowptr[N_NODES] = nE;
}

__global__ void scatter_kernel(const int* __restrict__ src,
                               const int* __restrict__ dst, int nE) {
    int e = blockIdx.x * blockDim.x + threadIdx.x;
    if (e < nE) {
        int d = dst[e];
        int pos = g_rowptr[d] + atomicAdd(&g_cursor[d], 1);
        g_col[pos] = src[e];
    }
}

// ---------------- fused aggregate + GEMM layer ------------------------------
// Warp per node. h rows are 64 floats; each lane holds features (2l, 2l+1) as
// a float2. Neighbor gather: coalesced 256B reads (L2-resident), dual
// accumulators for MLP=2. GEMM: W^T staged in shared as Wb[k][o]; each lane
// computes outputs (2l, 2l+1) so the float2 LDS from Wb is conflict-free and
// the h_neigh LDS is a broadcast.
template <int OUT, bool RELU>
__global__ void layer_kernel(const float* __restrict__ h,
                             const float* __restrict__ W,
                             const float* __restrict__ b,
                             float* __restrict__ out) {
    __shared__ float Wb[HID * OUT];
    __shared__ float bs[OUT];
    __shared__ float hn[8][HID];

    for (int idx = threadIdx.x; idx < OUT * HID; idx += blockDim.x) {
        int o = idx >> 6;       // row of W [OUT][64]
        int k = idx & 63;
        Wb[k * OUT + o] = W[idx];
    }
    for (int idx = threadIdx.x; idx < OUT; idx += blockDim.x) bs[idx] = b[idx];
    __syncthreads();

    const int warp = threadIdx.x >> 5;
    const int lane = threadIdx.x & 31;
    const int wpb = blockDim.x >> 5;  // 8

    for (int node = blockIdx.x * wpb + warp; node < N_NODES;
         node += gridDim.x * wpb) {
        // self term
        const float2* hv = (const float2*)(h + (size_t)node * HID);
        float2 a0 = hv[lane];
        float2 a1 = make_float2(0.0f, 0.0f);

        int s = g_rowptr[node];
        int e = g_rowptr[node + 1];
        int j = s;
        for (; j + 1 < e; j += 2) {
            int i0 = __ldg(&g_col[j]);
            int i1 = __ldg(&g_col[j + 1]);
            float2 v0 = ((const float2*)(h + (size_t)i0 * HID))[lane];
            float2 v1 = ((const float2*)(h + (size_t)i1 * HID))[lane];
            a0.x += v0.x; a0.y += v0.y;
            a1.x += v1.x; a1.y += v1.y;
        }
        if (j < e) {
            int i0 = __ldg(&g_col[j]);
            float2 v0 = ((const float2*)(h + (size_t)i0 * HID))[lane];
            a0.x += v0.x; a0.y += v0.y;
        }
        float iv = g_inv[node];
        float x0 = (a0.x + a1.x) * iv;
        float x1 = (a0.y + a1.y) * iv;
        hn[warp][2 * lane]     = x0;
        hn[warp][2 * lane + 1] = x1;
        __syncwarp();

        if (lane < OUT / 2) {
            float acc0 = bs[2 * lane];
            float acc1 = bs[2 * lane + 1];
#pragma unroll
            for (int k = 0; k < HID; k++) {
                float hk = hn[warp][k];
                float2 w = ((const float2*)(Wb + k * OUT))[lane];
                acc0 = fmaf(hk, w.x, acc0);
                acc1 = fmaf(hk, w.y, acc1);
            }
            if (RELU) { acc0 = fmaxf(acc0, 0.0f); acc1 = fmaxf(acc1, 0.0f); }
            float2* op = (float2*)(out + (size_t)node * OUT);
            op[lane] = make_float2(acc0, acc1);
        }
        __syncwarp();  // protect hn[warp] before next node's store
    }
}

// ---------------- launch ----------------------------------------------------
extern "C" void kernel_launch(void* const* d_in, const int* in_sizes, int n_in,
                              void* d_out, int out_size) {
    const float* features = (const float*)d_in[0];
    const int*   src      = (const int*)d_in[1];
    const int*   dst      = (const int*)d_in[2];
    const float* W0       = (const float*)d_in[3];
    const float* b0       = (const float*)d_in[4];
    const float* W1       = (const float*)d_in[5];
    const float* b1       = (const float*)d_in[6];
    const float* W2       = (const float*)d_in[7];
    const float* b2       = (const float*)d_in[8];
    float* out = (float*)d_out;

    const int nE = in_sizes[1];  // 1600000
    const int nb1 = (N_NODES + 1023) / 1024;  // 98

    // CSR build
    zero_deg_kernel<<<(N_NODES + 255) / 256, 256>>>();
    count_deg_kernel<<<(nE + 255) / 256, 256>>>(dst, nE);
    scan1_kernel<<<nb1, 1024>>>();
    scan2_kernel<<<1, 128>>>(nb1);
    scan3_kernel<<<(N_NODES + 255) / 256, 256>>>(nE);
    scatter_kernel<<<(nE + 255) / 256, 256>>>(src, dst, nE);

    // 3 fused layers
    const int blocks = 148 * 8;
    layer_kernel<HID, true ><<<blocks, 256>>>(features, W0, b0, g_h0);
    layer_kernel<HID, true ><<<blocks, 256>>>(g_h0,     W1, b1, g_h1);
    layer_kernel<N_CLS, false><<<blocks, 256>>>(g_h1,   W2, b2, out);
}

// round 2
// speedup vs baseline: 1.0005x; 1.0005x over previous
#include <cuda_runtime.h>
#include <cuda_bf16.h>
#include <cstdint>

#define N_NODES 100000
#define N_EDGES 1600000
#define HID 64
#define N_CLS 40

// ---------------- scratch (static device allocations; no cudaMalloc) -------
__device__ float g_h0[(size_t)N_NODES * HID];
__device__ float g_h1[(size_t)N_NODES * HID];
__device__ int   g_deg[N_NODES];
__device__ float g_inv[N_NODES];
__device__ int   g_rowptr[N_NODES + 1];
__device__ int   g_cursor[N_NODES];
__device__ int   g_col[N_EDGES];
__device__ int   g_bsums[128];
__device__ int   g_boffs[128];

// ---------------- CSR build ------------------------------------------------
__global__ void zero_deg_kernel() {
    int i = blockIdx.x * blockDim.x + threadIdx.x;
    if (i < N_NODES) g_deg[i] = 0;
}

__global__ void count_deg_kernel(const int* __restrict__ dst, int nE) {
    int e = blockIdx.x * blockDim.x + threadIdx.x;
    if (e < nE) atomicAdd(&g_deg[dst[e]], 1);
}

__device__ __forceinline__ int block_exscan(int val, int tid, int nthreads) {
    __shared__ int warp_s[32];
    int lane = tid & 31, wid = tid >> 5;
    int x = val;
#pragma unroll
    for (int d = 1; d < 32; d <<= 1) {
        int y = __shfl_up_sync(0xffffffffu, x, d);
        if (lane >= d) x += y;
    }
    if (lane == 31) warp_s[wid] = x;
    __syncthreads();
    int nw = nthreads >> 5;
    if (wid == 0) {
        int w = (lane < nw) ? warp_s[lane] : 0;
#pragma unroll
        for (int d = 1; d < 32; d <<= 1) {
            int y = __shfl_up_sync(0xffffffffu, w, d);
            if (lane >= d) w += y;
        }
        warp_s[lane] = w;  // inclusive scan of warp sums
    }
    __syncthreads();
    int base = (wid > 0) ? warp_s[wid - 1] : 0;
    return base + x - val;  // exclusive
}

__global__ void scan1_kernel() {
    int gid = blockIdx.x * 1024 + threadIdx.x;
    int v = (gid < N_NODES) ? g_deg[gid] : 0;
    int ex = block_exscan(v, threadIdx.x, 1024);
    if (gid < N_NODES) g_rowptr[gid] = ex;
    if (threadIdx.x == 1023) g_bsums[blockIdx.x] = ex + v;
}

__global__ void scan2_kernel(int nb) {
    int v = (threadIdx.x < nb) ? g_bsums[threadIdx.x] : 0;
    int ex = block_exscan(v, threadIdx.x, 128);
    if (threadIdx.x < nb) g_boffs[threadIdx.x] = ex;
}

__global__ void scan3_kernel(int nE) {
    int i = blockIdx.x * blockDim.x + threadIdx.x;
    if (i < N_NODES) {
        g_rowptr[i] += g_boffs[i >> 10];
        g_cursor[i] = 0;
        g_inv[i] = 1.0f / ((float)g_deg[i] + 1.0f);
    }
    if (i == 0) g_rowptr[N_NODES] = nE;
}

__global__ void scatter_kernel(const int* __restrict__ src,
                               const int* __restrict__ dst, int nE) {
    int e = blockIdx.x * blockDim.x + threadIdx.x;
    if (e < nE) {
        int d = dst[e];
        int pos = g_rowptr[d] + atomicAdd(&g_cursor[d], 1);
        g_col[pos] = src[e];
    }
}

// ---------------- fused aggregate + GEMM layer ------------------------------
// Warp per node. h rows are 64 floats; each lane holds features (2l, 2l+1) as
// a float2. Neighbor gather: coalesced 256B reads (L2-resident), dual
// accumulators for MLP=2. GEMM: W^T staged in shared as Wb[k][o]; each lane
// computes outputs (2l, 2l+1) so the float2 LDS from Wb is conflict-free and
// the h_neigh LDS is a broadcast.
template <int OUT, bool RELU>
__global__ void layer_kernel(const float* __restrict__ h,
                             const float* __restrict__ W,
                             const float* __restrict__ b,
                             float* __restrict__ out) {
    __shared__ float Wb[HID * OUT];
    __shared__ float bs[OUT];
    __shared__ float hn[8][HID];

    for (int idx = threadIdx.x; idx < OUT * HID; idx += blockDim.x) {
        int o = idx >> 6;       // row of W [OUT][64]
        int k = idx & 63;
        Wb[k * OUT + o] = W[idx];
    }
    for (int idx = threadIdx.x; idx < OUT; idx += blockDim.x) bs[idx] = b[idx];
    __syncthreads();

    const int warp = threadIdx.x >> 5;
    const int lane = threadIdx.x & 31;
    const int wpb = blockDim.x >> 5;  // 8

    for (int node = blockIdx.x * wpb + warp; node < N_NODES;
         node += gridDim.x * wpb) {
        // self term
        const float2* hv = (const float2*)(h + (size_t)node * HID);
        float2 a0 = hv[lane];
        float2 a1 = make_float2(0.0f, 0.0f);

        int s = g_rowptr[node];
        int e = g_rowptr[node + 1];
        int j = s;
        for (; j + 1 < e; j += 2) {
            int i0 = __ldg(&g_col[j]);
            int i1 = __ldg(&g_col[j + 1]);
            float2 v0 = ((const float2*)(h + (size_t)i0 * HID))[lane];
            float2 v1 = ((const float2*)(h + (size_t)i1 * HID))[lane];
            a0.x += v0.x; a0.y += v0.y;
            a1.x += v1.x; a1.y += v1.y;
        }
        if (j < e) {
            int i0 = __ldg(&g_col[j]);
            float2 v0 = ((const float2*)(h + (size_t)i0 * HID))[lane];
            a0.x += v0.x; a0.y += v0.y;
        }
        float iv = g_inv[node];
        float x0 = (a0.x + a1.x) * iv;
        float x1 = (a0.y + a1.y) * iv;
        hn[warp][2 * lane]     = x0;
        hn[warp][2 * lane + 1] = x1;
        __syncwarp();

        if (lane < OUT / 2) {
            float acc0 = bs[2 * lane];
            float acc1 = bs[2 * lane + 1];
#pragma unroll
            for (int k = 0; k < HID; k++) {
                float hk = hn[warp][k];
                float2 w = ((const float2*)(Wb + k * OUT))[lane];
                acc0 = fmaf(hk, w.x, acc0);
                acc1 = fmaf(hk, w.y, acc1);
            }
            if (RELU) { acc0 = fmaxf(acc0, 0.0f); acc1 = fmaxf(acc1, 0.0f); }
            float2* op = (float2*)(out + (size_t)node * OUT);
            op[lane] = make_float2(acc0, acc1);
        }
        __syncwarp();  // protect hn[warp] before next node's store
    }
}

// ---------------- launch ----------------------------------------------------
extern "C" void kernel_launch(void* const* d_in, const int* in_sizes, int n_in,
                              void* d_out, int out_size) {
    const float* features = (const float*)d_in[0];
    const int*   src      = (const int*)d_in[1];
    const int*   dst      = (const int*)d_in[2];
    const float* W0       = (const float*)d_in[3];
    const float* b0       = (const float*)d_in[4];
    const float* W1       = (const float*)d_in[5];
    const float* b1       = (const float*)d_in[6];
    const float* W2       = (const float*)d_in[7];
    const float* b2       = (const float*)d_in[8];
    float* out = (float*)d_out;

    const int nE = in_sizes[1];  // 1600000
    const int nb1 = (N_NODES + 1023) / 1024;  // 98

    // CSR build
    zero_deg_kernel<<<(N_NODES + 255) / 256, 256>>>();
    count_deg_kernel<<<(nE + 255) / 256, 256>>>(dst, nE);
    scan1_kernel<<<nb1, 1024>>>();
    scan2_kernel<<<1, 128>>>(nb1);
    scan3_kernel<<<(N_NODES + 255) / 256, 256>>>(nE);
    scatter_kernel<<<(nE + 255) / 256, 256>>>(src, dst, nE);

    // 3 fused layers
    const int blocks = 148 * 8;
    layer_kernel<HID, true ><<<blocks, 256>>>(features, W0, b0, g_h0);
    layer_kernel<HID, true ><<<blocks, 256>>>(g_h0,     W1, b1, g_h1);
    layer_kernel<N_CLS, false><<<blocks, 256>>>(g_h1,   W2, b2, out);
}

// round 3
// speedup vs baseline: 1.0019x; 1.0014x over previous
#include <cuda_runtime.h>
#include <cuda_bf16.h>
#include <cstdint>

#define N_NODES 100000
#define N_EDGES 1600000
#define HID 64
#define N_CLS 40

// ---------------- scratch (static device allocations; no cudaMalloc) -------
__device__ float g_h0[(size_t)N_NODES * HID];
__device__ float g_h1[(size_t)N_NODES * HID];
__device__ int   g_deg[N_NODES];
__device__ float g_inv[N_NODES];
__device__ int   g_rowptr[N_NODES + 1];
__device__ int   g_cursor[N_NODES];
__device__ int   g_col[N_EDGES];
__device__ int   g_bsums[128];
__device__ int   g_boffs[128];

// ---------------- CSR build ------------------------------------------------
__global__ void zero_deg_kernel() {
    int i = blockIdx.x * blockDim.x + threadIdx.x;
    if (i < N_NODES) g_deg[i] = 0;
}

__global__ void count_deg_kernel(const int* __restrict__ dst, int nE) {
    int e = blockIdx.x * blockDim.x + threadIdx.x;
    if (e < nE) atomicAdd(&g_deg[dst[e]], 1);
}

__device__ __forceinline__ int block_exscan(int val, int tid, int nthreads) {
    __shared__ int warp_s[32];
    int lane = tid & 31, wid = tid >> 5;
    int x = val;
#pragma unroll
    for (int d = 1; d < 32; d <<= 1) {
        int y = __shfl_up_sync(0xffffffffu, x, d);
        if (lane >= d) x += y;
    }
    if (lane == 31) warp_s[wid] = x;
    __syncthreads();
    int nw = nthreads >> 5;
    if (wid == 0) {
        int w = (lane < nw) ? warp_s[lane] : 0;
#pragma unroll
        for (int d = 1; d < 32; d <<= 1) {
            int y = __shfl_up_sync(0xffffffffu, w, d);
            if (lane >= d) w += y;
        }
        warp_s[lane] = w;  // inclusive scan of warp sums
    }
    __syncthreads();
    int base = (wid > 0) ? warp_s[wid - 1] : 0;
    return base + x - val;  // exclusive
}

__global__ void scan1_kernel() {
    int gid = blockIdx.x * 1024 + threadIdx.x;
    int v = (gid < N_NODES) ? g_deg[gid] : 0;
    int ex = block_exscan(v, threadIdx.x, 1024);
    if (gid < N_NODES) g_rowptr[gid] = ex;
    if (threadIdx.x == 1023) g_bsums[blockIdx.x] = ex + v;
}

__global__ void scan2_kernel(int nb) {
    int v = (threadIdx.x < nb) ? g_bsums[threadIdx.x] : 0;
    int ex = block_exscan(v, threadIdx.x, 128);
    if (threadIdx.x < nb) g_boffs[threadIdx.x] = ex;
}

__global__ void scan3_kernel(int nE) {
    int i = blockIdx.x * blockDim.x + threadIdx.x;
    if (i < N_NODES) {
        g_rowptr[i] += g_boffs[i >> 10];
        g_cursor[i] = 0;
        g_inv[i] = 1.0f / ((float)g_deg[i] + 1.0f);
    }
    if (i == 0) g_rowptr[N_NODES] = nE;
}

__global__ void scatter_kernel(const int* __restrict__ src,
                               const int* __restrict__ dst, int nE) {
    int e = blockIdx.x * blockDim.x + threadIdx.x;
    if (e < nE) {
        int d = dst[e];
        int pos = g_rowptr[d] + atomicAdd(&g_cursor[d], 1);
        g_col[pos] = src[e];
    }
}

// ---------------- fused aggregate + GEMM layer ------------------------------
// Warp per node. h rows are 64 floats; each lane holds features (2l, 2l+1) as
// a float2. Neighbor gather: coalesced 256B reads (L2-resident), dual
// accumulators for MLP=2. GEMM: W^T staged in shared as Wb[k][o]; each lane
// computes outputs (2l, 2l+1) so the float2 LDS from Wb is conflict-free and
// the h_neigh LDS is a broadcast.
template <int OUT, bool RELU>
__global__ void layer_kernel(const float* __restrict__ h,
                             const float* __restrict__ W,
                             const float* __restrict__ b,
                             float* __restrict__ out) {
    __shared__ float Wb[HID * OUT];
    __shared__ float bs[OUT];
    __shared__ float hn[8][HID];

    for (int idx = threadIdx.x; idx < OUT * HID; idx += blockDim.x) {
        int o = idx >> 6;       // row of W [OUT][64]
        int k = idx & 63;
        Wb[k * OUT + o] = W[idx];
    }
    for (int idx = threadIdx.x; idx < OUT; idx += blockDim.x) bs[idx] = b[idx];
    __syncthreads();

    const int warp = threadIdx.x >> 5;
    const int lane = threadIdx.x & 31;
    const int wpb = blockDim.x >> 5;  // 8

    for (int node = blockIdx.x * wpb + warp; node < N_NODES;
         node += gridDim.x * wpb) {
        // self term
        const float2* hv = (const float2*)(h + (size_t)node * HID);
        float2 a0 = hv[lane];
        float2 a1 = make_float2(0.0f, 0.0f);

        int s = g_rowptr[node];
        int e = g_rowptr[node + 1];
        int j = s;
        for (; j + 1 < e; j += 2) {
            int i0 = __ldg(&g_col[j]);
            int i1 = __ldg(&g_col[j + 1]);
            float2 v0 = ((const float2*)(h + (size_t)i0 * HID))[lane];
            float2 v1 = ((const float2*)(h + (size_t)i1 * HID))[lane];
            a0.x += v0.x; a0.y += v0.y;
            a1.x += v1.x; a1.y += v1.y;
        }
        if (j < e) {
            int i0 = __ldg(&g_col[j]);
            float2 v0 = ((const float2*)(h + (size_t)i0 * HID))[lane];
            a0.x += v0.x; a0.y += v0.y;
        }
        float iv = g_inv[node];
        float x0 = (a0.x + a1.x) * iv;
        float x1 = (a0.y + a1.y) * iv;
        hn[warp][2 * lane]     = x0;
        hn[warp][2 * lane + 1] = x1;
        __syncwarp();

        if (lane < OUT / 2) {
            float acc0 = bs[2 * lane];
            float acc1 = bs[2 * lane + 1];
#pragma unroll
            for (int k = 0; k < HID; k++) {
                float hk = hn[warp][k];
                float2 w = ((const float2*)(Wb + k * OUT))[lane];
                acc0 = fmaf(hk, w.x, acc0);
                acc1 = fmaf(hk, w.y, acc1);
            }
            if (RELU) { acc0 = fmaxf(acc0, 0.0f); acc1 = fmaxf(acc1, 0.0f); }
            float2* op = (float2*)(out + (size_t)node * OUT);
            op[lane] = make_float2(acc0, acc1);
        }
        __syncwarp();  // protect hn[warp] before next node's store
    }
}

// ---------------- launch ----------------------------------------------------
extern "C" void kernel_launch(void* const* d_in, const int* in_sizes, int n_in,
                              void* d_out, int out_size) {
    const float* features = (const float*)d_in[0];
    const int*   src      = (const int*)d_in[1];
    const int*   dst      = (const int*)d_in[2];
    const float* W0       = (const float*)d_in[3];
    const float* b0       = (const float*)d_in[4];
    const float* W1       = (const float*)d_in[5];
    const float* b1       = (const float*)d_in[6];
    const float* W2       = (const float*)d_in[7];
    const float* b2       = (const float*)d_in[8];
    float* out = (float*)d_out;

    const int nE = in_sizes[1];  // 1600000
    const int nb1 = (N_NODES + 1023) / 1024;  // 98

    // CSR build
    zero_deg_kernel<<<(N_NODES + 255) / 256, 256>>>();
    count_deg_kernel<<<(nE + 255) / 256, 256>>>(dst, nE);
    scan1_kernel<<<nb1, 1024>>>();
    scan2_kernel<<<1, 128>>>(nb1);
    scan3_kernel<<<(N_NODES + 255) / 256, 256>>>(nE);
    scatter_kernel<<<(nE + 255) / 256, 256>>>(src, dst, nE);

    // 3 fused layers
    const int blocks = 148 * 8;
    layer_kernel<HID, true ><<<blocks, 256>>>(features, W0, b0, g_h0);
    layer_kernel<HID, true ><<<blocks, 256>>>(g_h0,     W1, b1, g_h1);
    layer_kernel<N_CLS, false><<<blocks, 256>>>(g_h1,   W2, b2, out);
}

// round 4
// speedup vs baseline: 1.0025x; 1.0006x over previous
#include <cuda_runtime.h>
#include <cuda_bf16.h>
#include <cstdint>

#define N_NODES 100000
#define N_EDGES 1600000
#define HID 64
#define N_CLS 40

// ---------------- scratch (static device allocations; no cudaMalloc) -------
__device__ float g_h0[(size_t)N_NODES * HID];
__device__ float g_h1[(size_t)N_NODES * HID];
__device__ int   g_deg[N_NODES];
__device__ float g_inv[N_NODES];
__device__ int   g_rowptr[N_NODES + 1];
__device__ int   g_cursor[N_NODES];
__device__ int   g_col[N_EDGES];
__device__ int   g_bsums[128];
__device__ int   g_boffs[128];

// ---------------- CSR build ------------------------------------------------
__global__ void zero_deg_kernel() {
    int i = blockIdx.x * blockDim.x + threadIdx.x;
    if (i < N_NODES) g_deg[i] = 0;
}

__global__ void count_deg_kernel(const int* __restrict__ dst, int nE) {
    int e = blockIdx.x * blockDim.x + threadIdx.x;
    if (e < nE) atomicAdd(&g_deg[dst[e]], 1);
}

__device__ __forceinline__ int block_exscan(int val, int tid, int nthreads) {
    __shared__ int warp_s[32];
    int lane = tid & 31, wid = tid >> 5;
    int x = val;
#pragma unroll
    for (int d = 1; d < 32; d <<= 1) {
        int y = __shfl_up_sync(0xffffffffu, x, d);
        if (lane >= d) x += y;
    }
    if (lane == 31) warp_s[wid] = x;
    __syncthreads();
    int nw = nthreads >> 5;
    if (wid == 0) {
        int w = (lane < nw) ? warp_s[lane] : 0;
#pragma unroll
        for (int d = 1; d < 32; d <<= 1) {
            int y = __shfl_up_sync(0xffffffffu, w, d);
            if (lane >= d) w += y;
        }
        warp_s[lane] = w;  // inclusive scan of warp sums
    }
    __syncthreads();
    int base = (wid > 0) ? warp_s[wid - 1] : 0;
    return base + x - val;  // exclusive
}

__global__ void scan1_kernel() {
    int gid = blockIdx.x * 1024 + threadIdx.x;
    int v = (gid < N_NODES) ? g_deg[gid] : 0;
    int ex = block_exscan(v, threadIdx.x, 1024);
    if (gid < N_NODES) g_rowptr[gid] = ex;
    if (threadIdx.x == 1023) g_bsums[blockIdx.x] = ex + v;
}

__global__ void scan2_kernel(int nb) {
    int v = (threadIdx.x < nb) ? g_bsums[threadIdx.x] : 0;
    int ex = block_exscan(v, threadIdx.x, 128);
    if (threadIdx.x < nb) g_boffs[threadIdx.x] = ex;
}

__global__ void scan3_kernel(int nE) {
    int i = blockIdx.x * blockDim.x + threadIdx.x;
    if (i < N_NODES) {
        g_rowptr[i] += g_boffs[i >> 10];
        g_cursor[i] = 0;
        g_inv[i] = 1.0f / ((float)g_deg[i] + 1.0f);
    }
    if (i == 0) g_rowptr[N_NODES] = nE;
}

__global__ void scatter_kernel(const int* __restrict__ src,
                               const int* __restrict__ dst, int nE) {
    int e = blockIdx.x * blockDim.x + threadIdx.x;
    if (e < nE) {
        int d = dst[e];
        int pos = g_rowptr[d] + atomicAdd(&g_cursor[d], 1);
        g_col[pos] = src[e];
    }
}

// ---------------- fused aggregate + GEMM layer ------------------------------
// Warp per node. h rows are 64 floats; each lane holds features (2l, 2l+1) as
// a float2. Neighbor gather: coalesced 256B reads (L2-resident), dual
// accumulators for MLP=2. GEMM: W^T staged in shared as Wb[k][o]; each lane
// computes outputs (2l, 2l+1) so the float2 LDS from Wb is conflict-free and
// the h_neigh LDS is a broadcast.
template <int OUT, bool RELU>
__global__ void layer_kernel(const float* __restrict__ h,
                             const float* __restrict__ W,
                             const float* __restrict__ b,
                             float* __restrict__ out) {
    __shared__ float Wb[HID * OUT];
    __shared__ float bs[OUT];
    __shared__ float hn[8][HID];

    for (int idx = threadIdx.x; idx < OUT * HID; idx += blockDim.x) {
        int o = idx >> 6;       // row of W [OUT][64]
        int k = idx & 63;
        Wb[k * OUT + o] = W[idx];
    }
    for (int idx = threadIdx.x; idx < OUT; idx += blockDim.x) bs[idx] = b[idx];
    __syncthreads();

    const int warp = threadIdx.x >> 5;
    const int lane = threadIdx.x & 31;
    const int wpb = blockDim.x >> 5;  // 8

    for (int node = blockIdx.x * wpb + warp; node < N_NODES;
         node += gridDim.x * wpb) {
        // self term
        const float2* hv = (const float2*)(h + (size_t)node * HID);
        float2 a0 = hv[lane];
        float2 a1 = make_float2(0.0f, 0.0f);

        int s = g_rowptr[node];
        int e = g_rowptr[node + 1];
        int j = s;
        for (; j + 1 < e; j += 2) {
            int i0 = __ldg(&g_col[j]);
            int i1 = __ldg(&g_col[j + 1]);
            float2 v0 = ((const float2*)(h + (size_t)i0 * HID))[lane];
            float2 v1 = ((const float2*)(h + (size_t)i1 * HID))[lane];
            a0.x += v0.x; a0.y += v0.y;
            a1.x += v1.x; a1.y += v1.y;
        }
        if (j < e) {
            int i0 = __ldg(&g_col[j]);
            float2 v0 = ((const float2*)(h + (size_t)i0 * HID))[lane];
            a0.x += v0.x; a0.y += v0.y;
        }
        float iv = g_inv[node];
        float x0 = (a0.x + a1.x) * iv;
        float x1 = (a0.y + a1.y) * iv;
        hn[warp][2 * lane]     = x0;
        hn[warp][2 * lane + 1] = x1;
        __syncwarp();

        if (lane < OUT / 2) {
            float acc0 = bs[2 * lane];
            float acc1 = bs[2 * lane + 1];
#pragma unroll
            for (int k = 0; k < HID; k++) {
                float hk = hn[warp][k];
                float2 w = ((const float2*)(Wb + k * OUT))[lane];
                acc0 = fmaf(hk, w.x, acc0);
                acc1 = fmaf(hk, w.y, acc1);
            }
            if (RELU) { acc0 = fmaxf(acc0, 0.0f); acc1 = fmaxf(acc1, 0.0f); }
            float2* op = (float2*)(out + (size_t)node * OUT);
            op[lane] = make_float2(acc0, acc1);
        }
        __syncwarp();  // protect hn[warp] before next node's store
    }
}

// ---------------- launch ----------------------------------------------------
extern "C" void kernel_launch(void* const* d_in, const int* in_sizes, int n_in,
                              void* d_out, int out_size) {
    const float* features = (const float*)d_in[0];
    const int*   src      = (const int*)d_in[1];
    const int*   dst      = (const int*)d_in[2];
    const float* W0       = (const float*)d_in[3];
    const float* b0       = (const float*)d_in[4];
    const float* W1       = (const float*)d_in[5];
    const float* b1       = (const float*)d_in[6];
    const float* W2       = (const float*)d_in[7];
    const float* b2       = (const float*)d_in[8];
    float* out = (float*)d_out;

    const int nE = in_sizes[1];  // 1600000
    const int nb1 = (N_NODES + 1023) / 1024;  // 98

    // CSR build
    zero_deg_kernel<<<(N_NODES + 255) / 256, 256>>>();
    count_deg_kernel<<<(nE + 255) / 256, 256>>>(dst, nE);
    scan1_kernel<<<nb1, 1024>>>();
    scan2_kernel<<<1, 128>>>(nb1);
    scan3_kernel<<<(N_NODES + 255) / 256, 256>>>(nE);
    scatter_kernel<<<(nE + 255) / 256, 256>>>(src, dst, nE);

    // 3 fused layers
    const int blocks = 148 * 8;
    layer_kernel<HID, true ><<<blocks, 256>>>(features, W0, b0, g_h0);
    layer_kernel<HID, true ><<<blocks, 256>>>(g_h0,     W1, b1, g_h1);
    layer_kernel<N_CLS, false><<<blocks, 256>>>(g_h1,   W2, b2, out);
}